// round 7
// baseline (speedup 1.0000x reference)
#include <cuda_runtime.h>
#include <cuda_fp16.h>
#include <cstdint>

// Problem dims
constexpr int NB = 256, NT = 512, NF = 256, NH = 1024, NG = 4096;
constexpr int NOUT = 64;

// Recurrence tiling: K = NH = 1024 (x@W precomputed), fp16 mma + bulk loads
constexpr int BM = 64, BN = 128, BK = 128;
constexpr int NKT = NH / BK;             // 8
constexpr int NST = 3;
constexpr int A_BY = BM * BK * 2;        // 16384 B
constexpr int B_BY = BN * BK * 2;        // 32768 B
constexpr int ST_BY = A_BY + B_BY;       // 49152 B
constexpr int ST_H = ST_BY / 2;
constexpr int A_H = A_BY / 2;
constexpr int SMEM_BYTES = NST * ST_BY;  // 147456
constexpr int NCTAS = (NB / BM) * (NG / BN); // 128
constexpr int HSZ = 8 * NB * BK;         // halves per h buffer (262144)

// xz producer tiling
constexpr int XA_H = BM * BK;            // 8192 halves / A stage
constexpr int XB_H = BN * BK;            // 16384 halves / B buffer
constexpr int XSMEM = (3 * XA_H + 2 * XB_H) * 2; // 114688 B

// per-16 k permutation: position q holds k = PERM[q]
__device__ __constant__ int c_perm[16] = {0,1,8,9, 2,3,10,11, 4,5,12,13, 6,7,14,15};
__device__ __constant__ int c_pinv[16] = {0,1,4,5, 8,9,12,13, 2,3,6,7, 10,11,14,15};

// ---------------- device scratch ----------------
__device__ __half g_MB[(long)10 * NG * BK];      // [kt(10)][n][128] weights (kt 8,9 = W-part)
__device__ __half g_xB[(long)NT * 2 * NB * BK];  // [t][kb][b][128] fp16 x blocks
__device__ __half g_h[2 * HSZ];                  // ping-pong hidden, block layout
__device__ __half g_xz[(long)NT * 32 * 4 * 256 * 32]; // 1.07GB fragment-ordered xz+bias
__device__ float  g_bI[NG];
__device__ float  g_MLP[2048 * NH];
__device__ float  g_cf[NB * NH];                 // final c (fp32, for MLP)
__device__ float  g_hf[NB * NH];                 // final h (fp32, for MLP)
__device__ float  g_y1[NB * NH];
__device__ unsigned g_maskw[NB * 16];            // bit-packed mask [b][t/32]
__device__ unsigned g_bar = 0, g_gen = 0;

// ---------------- helpers ----------------
__device__ __forceinline__ unsigned smem_u32(const void* p) {
    unsigned a;
    asm("{ .reg .u64 t; cvta.to.shared.u64 t, %1; cvt.u32.u64 %0, t; }" : "=r"(a) : "l"(p));
    return a;
}
__device__ __forceinline__ float fex2(float x) {
    float y; asm("ex2.approx.f32 %0, %1;" : "=f"(y) : "f"(x)); return y;
}
__device__ __forceinline__ float frcp(float x) {
    float y; asm("rcp.approx.f32 %0, %1;" : "=f"(y) : "f"(x)); return y;
}
__device__ __forceinline__ float sigmf(float x) {
    return frcp(1.0f + fex2(-1.4426950408889634f * x));
}
__device__ __forceinline__ float tanhfa(float x) {
    return 1.0f - 2.0f * frcp(1.0f + fex2(2.8853900817779268f * x));
}
__device__ __forceinline__ void mma16(float* d, unsigned a0, unsigned a1, unsigned a2,
                                      unsigned a3, unsigned b0, unsigned b1) {
    asm volatile(
        "mma.sync.aligned.m16n8k16.row.col.f32.f16.f16.f32 "
        "{%0,%1,%2,%3}, {%4,%5,%6,%7}, {%8,%9}, {%0,%1,%2,%3};"
        : "+f"(d[0]), "+f"(d[1]), "+f"(d[2]), "+f"(d[3])
        : "r"(a0), "r"(a1), "r"(a2), "r"(a3), "r"(b0), "r"(b1));
}
__device__ __forceinline__ void mbar_init(unsigned mbar, unsigned cnt) {
    asm volatile("mbarrier.init.shared.b64 [%0], %1;" :: "r"(mbar), "r"(cnt) : "memory");
}
__device__ __forceinline__ void mbar_inval(unsigned mbar) {
    asm volatile("mbarrier.inval.shared.b64 [%0];" :: "r"(mbar) : "memory");
}
__device__ __forceinline__ void mbar_expect_tx(unsigned mbar, unsigned bytes) {
    asm volatile("mbarrier.arrive.expect_tx.shared.b64 _, [%0], %1;"
                 :: "r"(mbar), "r"(bytes) : "memory");
}
__device__ __forceinline__ void mbar_wait(unsigned mbar, unsigned parity) {
    asm volatile(
        "{\n\t.reg .pred P;\n"
        "W%=:\n\t"
        "mbarrier.try_wait.parity.acquire.cta.shared::cta.b64 P, [%0], %1, 0x989680;\n\t"
        "@!P bra W%=;\n\t}"
        :: "r"(mbar), "r"(parity) : "memory");
}
__device__ __forceinline__ void bulk_g2s(unsigned dst, const void* src, unsigned bytes,
                                         unsigned mbar) {
    asm volatile(
        "cp.async.bulk.shared::cta.global.mbarrier::complete_tx::bytes [%0], [%1], %2, [%3];"
        :: "r"(dst), "l"(src), "r"(bytes), "r"(mbar) : "memory");
}

__device__ __forceinline__ void grid_barrier() {
    __syncthreads();
    if (threadIdx.x == 0) {
        unsigned gen = *(volatile unsigned*)&g_gen;
        __threadfence();
        if (atomicAdd(&g_bar, 1u) == NCTAS - 1) {
            atomicExch(&g_bar, 0u);
            __threadfence();
            atomicAdd(&g_gen, 1u);
        } else {
            while (*(volatile unsigned*)&g_gen == gen) __nanosleep(64);
        }
        __threadfence();
    }
    __syncthreads();
}

// ---------------- mask (bit-packed; atomicOr is idempotent across replays) ----
__global__ void __launch_bounds__(256) mask_kernel(const float* __restrict__ x) {
    int warp = (blockIdx.x * 256 + threadIdx.x) >> 5;
    int lane = threadIdx.x & 31;
    if (warp >= NB * NT) return;
    int b = warp >> 9, t = warp & 511;
    const float4* p = (const float4*)(x + (long)warp * NF);
    float4 v1 = p[lane];
    float4 v2 = p[lane + 32];
    bool nz = v1.x != 0.f || v1.y != 0.f || v1.z != 0.f || v1.w != 0.f ||
              v2.x != 0.f || v2.y != 0.f || v2.z != 0.f || v2.w != 0.f;
    unsigned m = __ballot_sync(0xffffffffu, nz);
    if (lane == 0 && m != 0u)
        atomicOr(&g_maskw[b * 16 + (t >> 5)], 1u << (t & 31));
}

// ---------------- fused prep: weights + x conv + MLP combine + h0 ----------------
__global__ void __launch_bounds__(256) prep_all(
    const float* __restrict__ x, const float* __restrict__ W, const float* __restrict__ U,
    const float* __restrict__ b, const float* __restrict__ W1) {
    long idx = (long)blockIdx.x * 256 + threadIdx.x;
    const long R0 = (long)10 * NG * 128;        // 5242880 weights
    const long R1 = R0 + (long)NT * 2 * NB * 8; // + 2097152 x chunks
    const long R2 = R1 + (long)2048 * NH;       // + 2097152 mlp
    const long R3 = R2 + HSZ / 8;               // + 32768 h0 zero (uint4)
    if (idx < R0) {
        int hs = (int)(idx & 127);
        int n = (int)((idx >> 7) & (NG - 1));
        int kt = (int)(idx >> 19);
        int cc = (hs >> 4) ^ (n & 7);
        int hc = (cc << 4) | (hs & 15);
        int kl = (hc & ~15) | c_perm[hc & 15];
        int k = kt * BK + kl;
        int gate = n & 3, j = n >> 2;
        float v = (k < NH) ? U[(long)k * NG + gate * NH + j]
                           : W[(long)(k - NH) * NG + gate * NH + j];
        g_MB[idx] = __float2half_rn(v);
        if (hs == 0 && kt == 0) g_bI[n] = b[gate * NH + j];
    } else if (idx < R1) {
        long r = idx - R0;
        int cs = (int)(r & 7);
        int bb = (int)((r >> 3) & 255);
        int kb = (int)((r >> 11) & 1);
        int t = (int)(r >> 12);
        int cc = cs ^ (bb & 7);
        const float* src = x + ((long)bb * NT + t) * NF + kb * 128 + cc * 16;
        float4 v0 = *(const float4*)(src);
        float4 v1 = *(const float4*)(src + 4);
        float4 v2 = *(const float4*)(src + 8);
        float4 v3 = *(const float4*)(src + 12);
        __half2 h[8];
        h[0] = __floats2half2_rn(v0.x, v0.y);
        h[1] = __floats2half2_rn(v2.x, v2.y);
        h[2] = __floats2half2_rn(v0.z, v0.w);
        h[3] = __floats2half2_rn(v2.z, v2.w);
        h[4] = __floats2half2_rn(v1.x, v1.y);
        h[5] = __floats2half2_rn(v3.x, v3.y);
        h[6] = __floats2half2_rn(v1.z, v1.w);
        h[7] = __floats2half2_rn(v3.z, v3.w);
        __half* dst = g_xB + ((((long)t * 2 + kb) * NB + bb) * 128 + cs * 16);
        *(uint4*)(dst) = *(uint4*)(h);
        *(uint4*)(dst + 8) = *(uint4*)(h + 4);
    } else if (idx < R2) {
        long r = idx - R1;
        int k = (int)(r >> 10), m = (int)(r & (NH - 1));
        float v = (k < NH) ? (W1[(long)k * NH + m] + W1[(long)(k + NH) * NH + m])
                           : W1[(long)(k + NH) * NH + m];
        g_MLP[r] = v;
    } else if (idx < R3) {
        ((uint4*)g_h)[idx - R2] = make_uint4(0, 0, 0, 0);
    }
}

// ---------------- xz producer: xz[t] = x_t @ W + b, fragment-ordered fp16 --------
__global__ void __launch_bounds__(256) lstm_xz() {
    extern __shared__ __align__(128) char dsm[];
    __half* xs = (__half*)dsm;               // A0,A1,A2 | B0,B1
    __shared__ __align__(8) unsigned long long s_m[4];

    const int tid = threadIdx.x;
    const int lane = tid & 31;
    const int w = tid >> 5;
    const int wm = w & 1;
    const int wn = w >> 1;
    const int g = lane >> 2;
    const int c = lane & 3;
    const int c4 = 4 * c;
    const int bn = blockIdx.x * BN;
    const int bm = blockIdx.y * BM;
    const int t0 = blockIdx.z * 8;

    const unsigned smb = smem_u32(xs);
    const unsigned mbb = smem_u32(s_m);
    const unsigned mB = mbb + 24;

    if (tid == 0) {
        for (int s = 0; s < 3; ++s) mbar_init(mbb + 8 * s, 1);
        mbar_init(mB, 1);
    }
    __syncthreads();

    auto fillA = [&](int i) {
        int t = t0 + (i >> 1), kb = i & 1;
        unsigned mb = mbb + 8 * (i % 3);
        mbar_expect_tx(mb, (unsigned)(XA_H * 2));
        bulk_g2s(smb + (i % 3) * XA_H * 2,
                 g_xB + (((long)t * 2 + kb) * NB + bm) * 128, XA_H * 2, mb);
    };
    if (tid == 0) {
        mbar_expect_tx(mB, (unsigned)(2 * XB_H * 2));
        bulk_g2s(smb + 3 * XA_H * 2, g_MB + ((long)8 * NG + bn) * 128, XB_H * 2, mB);
        bulk_g2s(smb + (3 * XA_H + XB_H) * 2, g_MB + ((long)9 * NG + bn) * 128, XB_H * 2, mB);
        fillA(0);
        fillA(1);
    }

    float2 bb[4];
#pragma unroll
    for (int nt = 0; nt < 4; ++nt)
        bb[nt] = *(const float2*)(g_bI + bn + wn * 32 + nt * 8 + 2 * c);

    mbar_wait(mB, 0);
    int ph[3] = {0, 0, 0};

    for (int tt = 0; tt < 8; ++tt) {
        float acc[2][4][4];
#pragma unroll
        for (int i = 0; i < 2; ++i)
#pragma unroll
            for (int j = 0; j < 4; ++j)
#pragma unroll
                for (int k = 0; k < 4; ++k) acc[i][j][k] = 0.0f;

        for (int kb = 0; kb < 2; ++kb) {
            const int i = tt * 2 + kb, s = i % 3;
            mbar_wait(mbb + 8 * s, (unsigned)ph[s]);
            ph[s] ^= 1;
            __syncthreads();
            if (tid == 0 && i + 2 < 16) fillA(i + 2);

            const __half* arow = xs + s * XA_H + (wm * 32 + g) * 128;
            const __half* brow = xs + 3 * XA_H + kb * XB_H + (wn * 32 + g) * 128;
#pragma unroll
            for (int ch = 0; ch < 8; ++ch) {
                const int o = ((ch ^ g) << 4) + c4;
                uint2 aA = *(const uint2*)(arow + o);
                uint2 aB = *(const uint2*)(arow + 1024 + o);
                uint2 aC = *(const uint2*)(arow + 2048 + o);
                uint2 aD = *(const uint2*)(arow + 3072 + o);
                uint2 b0 = *(const uint2*)(brow + o);
                uint2 b1 = *(const uint2*)(brow + 1024 + o);
                uint2 b2 = *(const uint2*)(brow + 2048 + o);
                uint2 b3 = *(const uint2*)(brow + 3072 + o);
                mma16(acc[0][0], aA.x, aB.x, aA.y, aB.y, b0.x, b0.y);
                mma16(acc[0][1], aA.x, aB.x, aA.y, aB.y, b1.x, b1.y);
                mma16(acc[0][2], aA.x, aB.x, aA.y, aB.y, b2.x, b2.y);
                mma16(acc[0][3], aA.x, aB.x, aA.y, aB.y, b3.x, b3.y);
                mma16(acc[1][0], aC.x, aD.x, aC.y, aD.y, b0.x, b0.y);
                mma16(acc[1][1], aC.x, aD.x, aC.y, aD.y, b1.x, b1.y);
                mma16(acc[1][2], aC.x, aD.x, aC.y, aD.y, b2.x, b2.y);
                mma16(acc[1][3], aC.x, aD.x, aC.y, aD.y, b3.x, b3.y);
            }
        }

        // store fragment-ordered xz + bias (fp16)
        __half2 o[16];
#pragma unroll
        for (int mt = 0; mt < 2; ++mt)
#pragma unroll
            for (int nt = 0; nt < 4; ++nt) {
                o[(mt * 4 + nt) * 2]     = __floats2half2_rn(acc[mt][nt][0] + bb[nt].x,
                                                             acc[mt][nt][1] + bb[nt].y);
                o[(mt * 4 + nt) * 2 + 1] = __floats2half2_rn(acc[mt][nt][2] + bb[nt].x,
                                                             acc[mt][nt][3] + bb[nt].y);
            }
        __half* dst = g_xz + (((((long)(t0 + tt) * 32 + blockIdx.x) * 4 + blockIdx.y) << 13)
                              + tid * 32);
        const uint4* ov = (const uint4*)o;
        *(uint4*)(dst)      = ov[0];
        *(uint4*)(dst + 8)  = ov[1];
        *(uint4*)(dst + 16) = ov[2];
        *(uint4*)(dst + 24) = ov[3];
    }

    __syncthreads();
    if (tid == 0)
        for (int s = 0; s < 4; ++s) mbar_inval(mbb + 8 * s);
}

// ---------------- persistent LSTM recurrence (K=1024, register state) ------------
__global__ void __launch_bounds__(256) lstm_persistent() {
    extern __shared__ __align__(128) char dsm[];
    __half* sh = (__half*)dsm;
    __shared__ __align__(8) unsigned long long s_mbar[NST];

    const int tid = threadIdx.x;
    const int lane = tid & 31;
    const int w = tid >> 5;
    const int wm = w & 1;
    const int wn = w >> 1;
    const int bn = blockIdx.x * BN;
    const int bm = blockIdx.y * BM;
    const int g = lane >> 2;
    const int c = lane & 3;
    const int c4 = 4 * c;
    const int odd = c & 1;

    const unsigned smb = smem_u32(sh);
    const unsigned mbb = smem_u32(s_mbar);

    if (tid == 0)
        for (int s = 0; s < NST; ++s) mbar_init(mbb + 8 * s, 1);
    __syncthreads();

    // precompute per-fragment identities (t-independent)
    const int bgA = bm + wm * 32 + g + (odd ? 8 : 0);  // row for mt=0
    const int bgB = bgA + 16;                          // row for mt=1
    int hpos[8], jj[8];
#pragma unroll
    for (int i = 0; i < 8; ++i) {
        int mt = i >> 2, nt = i & 3;
        int bg = mt ? bgB : bgA;
        int j = (bn >> 2) + wn * 8 + nt * 2 + (c >> 1);
        jj[i] = j;
        int q = (j & ~15) | c_pinv[j & 15];
        int kb = q >> 7, hc = q & 127;
        hpos[i] = (((kb * NB + bg) << 7) + (((hc >> 4) ^ (bg & 7)) << 4) + (hc & 15));
    }
    float cst[8], hst[8];
#pragma unroll
    for (int i = 0; i < 8; ++i) { cst[i] = 0.0f; hst[i] = 0.0f; }

    const long xzbase = (((long)blockIdx.x * 4 + blockIdx.y) << 13) + tid * 32;
    int ph[NST] = {0, 0, 0};
    unsigned mw0 = 0, mw1 = 0;

    for (int t = 0; t < NT; ++t) {
        const int cur = t & 1;
        const __half* __restrict__ hsrc = g_h + cur * HSZ;
        __half* __restrict__ hdst = g_h + (cur ^ 1) * HSZ;

        if ((t & 31) == 0) {
            mw0 = g_maskw[bgA * 16 + (t >> 5)];
            mw1 = g_maskw[bgB * 16 + (t >> 5)];
        }

        auto fill = [&](int kt, int s) {
            unsigned mb = mbb + 8 * s;
            mbar_expect_tx(mb, (unsigned)ST_BY);
            bulk_g2s(smb + s * ST_BY, hsrc + ((long)kt * NB + bm) * BK, A_BY, mb);
            bulk_g2s(smb + s * ST_BY + A_BY, g_MB + ((long)kt * NG + bn) * BK, B_BY, mb);
        };
        if (tid == 0) { fill(0, 0); fill(1, 1); }

        // xz fragment loads (consumed in epilogue — fully overlapped)
        const __half* xzp = g_xz + ((long)t * 32 * 8192 * 4) + xzbase;
        uint4 q0 = *(const uint4*)(xzp);
        uint4 q1 = *(const uint4*)(xzp + 8);
        uint4 q2 = *(const uint4*)(xzp + 16);
        uint4 q3 = *(const uint4*)(xzp + 24);

        float acc[2][4][4];
#pragma unroll
        for (int i = 0; i < 2; ++i)
#pragma unroll
            for (int j = 0; j < 4; ++j)
#pragma unroll
                for (int k = 0; k < 4; ++k) acc[i][j][k] = 0.0f;

        for (int kt = 0; kt < NKT; ++kt) {
            const int s = kt % NST;
            mbar_wait(mbb + 8 * s, (unsigned)ph[s]);
            ph[s] ^= 1;
            __syncthreads();
            if (tid == 0 && kt + 2 < NKT) fill(kt + 2, (kt + 2) % NST);

            const __half* Ab = sh + s * ST_H;
            const __half* arow = Ab + (wm * 32 + g) * BK;
            const __half* brow = Ab + A_H + (wn * 32 + g) * BK;
#pragma unroll
            for (int ch = 0; ch < 8; ++ch) {
                const int o = ((ch ^ g) << 4) + c4;
                uint2 aA = *(const uint2*)(arow + o);
                uint2 aB = *(const uint2*)(arow + 1024 + o);
                uint2 aC = *(const uint2*)(arow + 2048 + o);
                uint2 aD = *(const uint2*)(arow + 3072 + o);
                uint2 b0 = *(const uint2*)(brow + o);
                uint2 b1 = *(const uint2*)(brow + 1024 + o);
                uint2 b2 = *(const uint2*)(brow + 2048 + o);
                uint2 b3 = *(const uint2*)(brow + 3072 + o);
                mma16(acc[0][0], aA.x, aB.x, aA.y, aB.y, b0.x, b0.y);
                mma16(acc[0][1], aA.x, aB.x, aA.y, aB.y, b1.x, b1.y);
                mma16(acc[0][2], aA.x, aB.x, aA.y, aB.y, b2.x, b2.y);
                mma16(acc[0][3], aA.x, aB.x, aA.y, aB.y, b3.x, b3.y);
                mma16(acc[1][0], aC.x, aD.x, aC.y, aD.y, b0.x, b0.y);
                mma16(acc[1][1], aC.x, aD.x, aC.y, aD.y, b1.x, b1.y);
                mma16(acc[1][2], aC.x, aD.x, aC.y, aD.y, b2.x, b2.y);
                mma16(acc[1][3], aC.x, aD.x, aC.y, aD.y, b3.x, b3.y);
            }
        }

        // add xz (fragment order), shuffle gate-quads, update register state
        {
            const __half2* xh = (const __half2*)&q0;  // q0..q3 contiguous on stack
            uint4 qq[4] = {q0, q1, q2, q3};
            xh = (const __half2*)qq;
#pragma unroll
            for (int mt = 0; mt < 2; ++mt)
#pragma unroll
                for (int nt = 0; nt < 4; ++nt) {
                    float2 a = __half22float2(xh[(mt * 4 + nt) * 2]);
                    float2 d = __half22float2(xh[(mt * 4 + nt) * 2 + 1]);
                    acc[mt][nt][0] += a.x;
                    acc[mt][nt][1] += a.y;
                    acc[mt][nt][2] += d.x;
                    acc[mt][nt][3] += d.y;
                }
        }

        unsigned bit0 = (mw0 >> (t & 31)) & 1u;
        unsigned bit1 = (mw1 >> (t & 31)) & 1u;
#pragma unroll
        for (int i = 0; i < 8; ++i) {
            int mt = i >> 2, nt = i & 3;
            float v0 = acc[mt][nt][0], v1 = acc[mt][nt][1];
            float v2 = acc[mt][nt][2], v3 = acc[mt][nt][3];
            float sx = odd ? v0 : v2;
            float sy = odd ? v1 : v3;
            float gx = __shfl_xor_sync(0xffffffffu, sx, 1);
            float gy = __shfl_xor_sync(0xffffffffu, sy, 1);
            float zi, zf, zg, zo;
            if (!odd) { zi = v0; zf = v1; zg = gx; zo = gy; }
            else      { zi = gx; zf = gy; zg = v2; zo = v3; }
            float iv = sigmf(zi), fv = sigmf(zf), gv = tanhfa(zg), ov = sigmf(zo);
            float cn = fv * cst[i] + iv * gv;
            float hn = ov * tanhfa(cn);
            unsigned msk = mt ? bit1 : bit0;
            if (!msk) { cn = cst[i]; hn = hst[i]; }
            cst[i] = cn;
            hst[i] = hn;
            hdst[hpos[i]] = __float2half_rn(hn);
        }

        grid_barrier();
    }

    // write final c (fp32) for the MLP head
#pragma unroll
    for (int i = 0; i < 8; ++i) {
        int bg = (i >> 2) ? bgB : bgA;
        g_cf[(long)bg * NH + jj[i]] = cst[i];
    }
    if (tid == 0)
        for (int s = 0; s < NST; ++s) mbar_inval(mbb + 8 * s);
}

// un-permute/un-swizzle final h (in g_h[0] after 512 steps) to fp32
__global__ void __launch_bounds__(256) unperm_h() {
    int idx = blockIdx.x * 256 + threadIdx.x; // NB*NH
    int b = idx >> 10, j = idx & 1023;
    int q = (j & ~15) | c_pinv[j & 15];
    int kb = q >> 7, hc = q & 127;
    long off = (((long)kb * NB + b) << 7) + (((hc >> 4) ^ (b & 7)) << 4) + (hc & 15);
    g_hf[idx] = __half2float(g_h[off]);
}

// ---------------- MLP head ----------------
__global__ void __launch_bounds__(256) mlp1_kernel(const float* __restrict__ b1) {
    __shared__ float a_s[64 * 20];
    __shared__ float b_s[16 * 68];
    int tid = threadIdx.x;
    int bn = blockIdx.x * 64, bm = blockIdx.y * 64;
    int ty = tid >> 4, tx = tid & 15;
    float acc[4][4];
#pragma unroll
    for (int i = 0; i < 4; ++i)
#pragma unroll
        for (int j = 0; j < 4; ++j) acc[i][j] = 0.0f;

    for (int kt = 0; kt < 128; ++kt) {
        int k0 = kt * 16;
        {
            int m = tid >> 2, kq = tid & 3;
            int k = k0 + 4 * kq;
            const float* src = (k < NH) ? (g_hf + (long)(bm + m) * NH + k)
                                        : (g_cf + (long)(bm + m) * NH + (k - NH));
            *(float4*)(a_s + m * 20 + 4 * kq) = *(const float4*)src;
        }
        {
            int kr = tid >> 4, cq = tid & 15;
            *(float4*)(b_s + kr * 68 + 4 * cq) =
                *(const float4*)(g_MLP + (long)(k0 + kr) * NH + bn + 4 * cq);
        }
        __syncthreads();
#pragma unroll
        for (int k = 0; k < 16; ++k) {
            float ar[4], br[4];
#pragma unroll
            for (int i = 0; i < 4; ++i) {
                ar[i] = a_s[(4 * ty + i) * 20 + k];
                br[i] = b_s[k * 68 + 4 * tx + i];
            }
#pragma unroll
            for (int i = 0; i < 4; ++i)
#pragma unroll
                for (int j = 0; j < 4; ++j) acc[i][j] += ar[i] * br[j];
        }
        __syncthreads();
    }
#pragma unroll
    for (int i = 0; i < 4; ++i)
#pragma unroll
        for (int j = 0; j < 4; ++j) {
            float v = acc[i][j] + b1[bn + 4 * tx + j];
            v = v > 0.0f ? v : 0.2f * v;
            g_y1[(long)(bm + 4 * ty + i) * NH + bn + 4 * tx + j] = v;
        }
}

__global__ void __launch_bounds__(64) mlp2_kernel(
    const float* __restrict__ W2, const float* __restrict__ b2, float* __restrict__ out) {
    __shared__ float row[NH];
    int bg = blockIdx.x;
    int o = threadIdx.x;
    for (int i = o; i < NH; i += 64) row[i] = g_y1[(long)bg * NH + i];
    __syncthreads();
    float acc = b2[o];
#pragma unroll 8
    for (int k = 0; k < NH; ++k) acc += row[k] * W2[(long)k * NOUT + o];
    out[(long)bg * NOUT + o] = acc;
}

// ---------------- launch ----------------
extern "C" void kernel_launch(void* const* d_in, const int* in_sizes, int n_in,
                              void* d_out, int out_size) {
    const float* x  = (const float*)d_in[0];
    const float* W  = (const float*)d_in[1];
    const float* U  = (const float*)d_in[2];
    const float* b  = (const float*)d_in[3];
    const float* W1 = (const float*)d_in[4];
    const float* b1 = (const float*)d_in[5];
    const float* W2 = (const float*)d_in[6];
    const float* b2 = (const float*)d_in[7];
    float* out = (float*)d_out;

    cudaFuncSetAttribute(lstm_persistent,
                         cudaFuncAttributeMaxDynamicSharedMemorySize, SMEM_BYTES);
    cudaFuncSetAttribute(lstm_xz,
                         cudaFuncAttributeMaxDynamicSharedMemorySize, XSMEM);

    const long PREP_N = (long)10 * NG * 128 + (long)NT * 2 * NB * 8 +
                        (long)2048 * NH + HSZ / 8;

    mask_kernel<<<(NB * NT * 32) / 256, 256>>>(x);
    prep_all<<<(int)((PREP_N + 255) / 256), 256>>>(x, W, U, b, W1);
    lstm_xz<<<dim3(NG / BN, NB / BM, NT / 8), 256, XSMEM>>>();
    lstm_persistent<<<dim3(NG / BN, NB / BM), 256, SMEM_BYTES>>>();
    unperm_h<<<(NB * NH) / 256, 256>>>();
    mlp1_kernel<<<dim3(NH / 64, NB / 64), 256>>>(b1);
    mlp2_kernel<<<NB, 64>>>(W2, b2, out);
}

// round 8
// speedup vs baseline: 1.5743x; 1.5743x over previous
#include <cuda_runtime.h>
#include <cuda_fp16.h>
#include <cstdint>

// Problem dims
constexpr int NB = 256, NT = 512, NF = 256, NH = 1024, NG = 4096;
constexpr int NKD = NH + NF; // 1280
constexpr int NOUT = 64;

// Persistent step-GEMM tiling (fp16 mma.sync + cp.async.bulk stage loads)
constexpr int BM = 64, BN = 128, BK = 128;
constexpr int NKT = NKD / BK;   // 10 (kt 0..7 = h blocks, 8..9 = x blocks)
constexpr int NST = 3;
constexpr int A_BY = BM * BK * 2;        // 16384 B
constexpr int B_BY = BN * BK * 2;        // 32768 B
constexpr int ST_BY = A_BY + B_BY;       // 49152 B
constexpr int ST_H = ST_BY / 2;
constexpr int A_H = A_BY / 2;
constexpr int SMEM_BYTES = NST * ST_BY;  // 147456
constexpr int NCTAS = (NB / BM) * (NG / BN); // 128
constexpr int HSZ = 8 * NB * BK;         // halves per h buffer

// per-16 k permutation: position q holds k = PERM[q]
__device__ __constant__ int c_perm[16] = {0,1,8,9, 2,3,10,11, 4,5,12,13, 6,7,14,15};
__device__ __constant__ int c_pinv[16] = {0,1,4,5, 8,9,12,13, 2,3,6,7, 10,11,14,15};

// ---------------- device scratch ----------------
__device__ __half g_MB[(long)10 * NG * BK];      // [kt(10)][n][128] weights (kt8,9 = W-part)
__device__ __half g_xB[(long)NT * 2 * NB * BK];  // [t][kb][b][128] fp16 x blocks
__device__ __half g_h[2 * HSZ];                  // ping-pong hidden, block layout
__device__ float  g_bI[NG];
__device__ float  g_MLP[2048 * NH];
__device__ float  g_cf[NB * NH];                 // final c (fp32)
__device__ float  g_hf[NB * NH];                 // final h (fp32)
__device__ float  g_y1[NB * NH];
__device__ unsigned g_maskw[NB * 16];            // bit-packed mask [b][t/32]
__device__ unsigned g_bar = 0, g_gen = 0;

// ---------------- helpers ----------------
__device__ __forceinline__ unsigned smem_u32(const void* p) {
    unsigned a;
    asm("{ .reg .u64 t; cvta.to.shared.u64 t, %1; cvt.u32.u64 %0, t; }" : "=r"(a) : "l"(p));
    return a;
}
__device__ __forceinline__ float fex2(float x) {
    float y; asm("ex2.approx.f32 %0, %1;" : "=f"(y) : "f"(x)); return y;
}
__device__ __forceinline__ float frcp(float x) {
    float y; asm("rcp.approx.f32 %0, %1;" : "=f"(y) : "f"(x)); return y;
}
__device__ __forceinline__ float sigmf(float x) {
    return frcp(1.0f + fex2(-1.4426950408889634f * x));
}
__device__ __forceinline__ float tanhfa(float x) {
    return 1.0f - 2.0f * frcp(1.0f + fex2(2.8853900817779268f * x));
}
__device__ __forceinline__ void mma16(float* d, unsigned a0, unsigned a1, unsigned a2,
                                      unsigned a3, unsigned b0, unsigned b1) {
    asm volatile(
        "mma.sync.aligned.m16n8k16.row.col.f32.f16.f16.f32 "
        "{%0,%1,%2,%3}, {%4,%5,%6,%7}, {%8,%9}, {%0,%1,%2,%3};"
        : "+f"(d[0]), "+f"(d[1]), "+f"(d[2]), "+f"(d[3])
        : "r"(a0), "r"(a1), "r"(a2), "r"(a3), "r"(b0), "r"(b1));
}
__device__ __forceinline__ void mbar_init(unsigned mbar, unsigned cnt) {
    asm volatile("mbarrier.init.shared.b64 [%0], %1;" :: "r"(mbar), "r"(cnt) : "memory");
}
__device__ __forceinline__ void mbar_inval(unsigned mbar) {
    asm volatile("mbarrier.inval.shared.b64 [%0];" :: "r"(mbar) : "memory");
}
__device__ __forceinline__ void mbar_expect_tx(unsigned mbar, unsigned bytes) {
    asm volatile("mbarrier.arrive.expect_tx.shared.b64 _, [%0], %1;"
                 :: "r"(mbar), "r"(bytes) : "memory");
}
__device__ __forceinline__ void mbar_wait(unsigned mbar, unsigned parity) {
    asm volatile(
        "{\n\t.reg .pred P;\n"
        "W%=:\n\t"
        "mbarrier.try_wait.parity.acquire.cta.shared::cta.b64 P, [%0], %1, 0x989680;\n\t"
        "@!P bra W%=;\n\t}"
        :: "r"(mbar), "r"(parity) : "memory");
}
__device__ __forceinline__ void bulk_g2s(unsigned dst, const void* src, unsigned bytes,
                                         unsigned mbar) {
    asm volatile(
        "cp.async.bulk.shared::cta.global.mbarrier::complete_tx::bytes [%0], [%1], %2, [%3];"
        :: "r"(dst), "l"(src), "r"(bytes), "r"(mbar) : "memory");
}

__device__ __forceinline__ void grid_barrier() {
    __syncthreads();
    if (threadIdx.x == 0) {
        unsigned gen = *(volatile unsigned*)&g_gen;
        __threadfence();
        if (atomicAdd(&g_bar, 1u) == NCTAS - 1) {
            atomicExch(&g_bar, 0u);
            __threadfence();
            atomicAdd(&g_gen, 1u);
        } else {
            while (*(volatile unsigned*)&g_gen == gen) __nanosleep(64);
        }
        __threadfence();
    }
    __syncthreads();
}

// ---------------- mask (bit-packed; atomicOr idempotent across replays) ----
__global__ void __launch_bounds__(256) mask_kernel(const float* __restrict__ x) {
    int warp = (blockIdx.x * 256 + threadIdx.x) >> 5;
    int lane = threadIdx.x & 31;
    if (warp >= NB * NT) return;
    int b = warp >> 9, t = warp & 511;
    const float4* p = (const float4*)(x + (long)warp * NF);
    float4 v1 = p[lane];
    float4 v2 = p[lane + 32];
    bool nz = v1.x != 0.f || v1.y != 0.f || v1.z != 0.f || v1.w != 0.f ||
              v2.x != 0.f || v2.y != 0.f || v2.z != 0.f || v2.w != 0.f;
    unsigned m = __ballot_sync(0xffffffffu, nz);
    if (lane == 0 && m != 0u)
        atomicOr(&g_maskw[b * 16 + (t >> 5)], 1u << (t & 31));
}

// ---------------- prep: weights (block layout, swizzled, permuted) ----------------
__global__ void __launch_bounds__(256) prep_weights(
    const float* __restrict__ W, const float* __restrict__ U, const float* __restrict__ b) {
    long idx = (long)blockIdx.x * 256 + threadIdx.x; // 10*NG*128
    int hs = (int)(idx & 127);
    int n = (int)((idx >> 7) & (NG - 1));
    int kt = (int)(idx >> 19);
    int cc = (hs >> 4) ^ (n & 7);
    int hc = (cc << 4) | (hs & 15);
    int kl = (hc & ~15) | c_perm[hc & 15];
    int k = kt * BK + kl;
    int gate = n & 3, j = n >> 2;
    float v = (k < NH) ? U[(long)k * NG + gate * NH + j]
                       : W[(long)(k - NH) * NG + gate * NH + j];
    g_MB[idx] = __float2half_rn(v);
    if (hs == 0 && kt == 0) g_bI[n] = b[gate * NH + j];
}

// ---------------- prep: x blocks + MLP combine + h0 zero ----------------
__global__ void __launch_bounds__(256) prep_misc(
    const float* __restrict__ x, const float* __restrict__ W1) {
    const long N0 = (long)NT * 2 * NB * 8;  // x chunks of 16 halves
    const long N1 = (long)2048 * NH;
    const long N2 = (long)HSZ / 8;          // h0 zero in uint4 units
    long idx = (long)blockIdx.x * 256 + threadIdx.x;
    if (idx < N0) {
        int cs = (int)(idx & 7);
        int bb = (int)((idx >> 3) & 255);
        int kb = (int)((idx >> 11) & 1);
        int t = (int)(idx >> 12);
        int cc = cs ^ (bb & 7);
        const float* src = x + ((long)bb * NT + t) * NF + kb * 128 + cc * 16;
        float4 v0 = *(const float4*)(src);
        float4 v1 = *(const float4*)(src + 4);
        float4 v2 = *(const float4*)(src + 8);
        float4 v3 = *(const float4*)(src + 12);
        __half2 h[8];
        h[0] = __floats2half2_rn(v0.x, v0.y);
        h[1] = __floats2half2_rn(v2.x, v2.y);
        h[2] = __floats2half2_rn(v0.z, v0.w);
        h[3] = __floats2half2_rn(v2.z, v2.w);
        h[4] = __floats2half2_rn(v1.x, v1.y);
        h[5] = __floats2half2_rn(v3.x, v3.y);
        h[6] = __floats2half2_rn(v1.z, v1.w);
        h[7] = __floats2half2_rn(v3.z, v3.w);
        __half* dst = g_xB + ((((long)t * 2 + kb) * NB + bb) * 128 + cs * 16);
        *(uint4*)(dst) = *(uint4*)(h);
        *(uint4*)(dst + 8) = *(uint4*)(h + 4);
    } else if (idx < N0 + N1) {
        long r = idx - N0;
        int k = (int)(r >> 10), m = (int)(r & (NH - 1));
        float v = (k < NH) ? (W1[(long)k * NH + m] + W1[(long)(k + NH) * NH + m])
                           : W1[(long)(k + NH) * NH + m];
        g_MLP[r] = v;
    } else if (idx < N0 + N1 + N2) {
        ((uint4*)g_h)[idx - N0 - N1] = make_uint4(0, 0, 0, 0);
    }
}

// ---------------- persistent LSTM recurrence ----------------
__global__ void __launch_bounds__(256) lstm_persistent() {
    extern __shared__ __align__(128) char dsm[];
    __half* sh = (__half*)dsm;
    __shared__ __align__(8) unsigned long long s_mbar[NST];

    const int tid = threadIdx.x;
    const int lane = tid & 31;
    const int w = tid >> 5;
    const int wm = w & 1;
    const int wn = w >> 1;
    const int bn = blockIdx.x * BN;
    const int bm = blockIdx.y * BM;
    const int g = lane >> 2;
    const int c = lane & 3;
    const int c4 = 4 * c;
    const int odd = c & 1;

    const unsigned smb = smem_u32(sh);
    const unsigned mbb = smem_u32(s_mbar);

    if (tid == 0)
        for (int s = 0; s < NST; ++s) mbar_init(mbb + 8 * s, 1);
    __syncthreads();

    // fragment identities (t-independent). Even lanes own rows g, odd rows g+8.
    const int bgA = bm + wm * 32 + g + (odd ? 8 : 0);
    const int bgB = bgA + 16;
    int jj[4], hposA[4], hposB[4];
    float4 b4[4];
#pragma unroll
    for (int nt = 0; nt < 4; ++nt) {
        int j = (bn >> 2) + wn * 8 + nt * 2 + (c >> 1);
        jj[nt] = j;
        int q = (j & ~15) | c_pinv[j & 15];
        int kb = q >> 7, hc = q & 127;
        hposA[nt] = ((kb * NB + bgA) << 7) + (((hc >> 4) ^ (bgA & 7)) << 4) + (hc & 15);
        hposB[nt] = ((kb * NB + bgB) << 7) + (((hc >> 4) ^ (bgB & 7)) << 4) + (hc & 15);
        b4[nt] = *(const float4*)(g_bI + 4 * j);
    }
    float cst[8], hst[8];
#pragma unroll
    for (int i = 0; i < 8; ++i) { cst[i] = 0.0f; hst[i] = 0.0f; }

    int ph[NST] = {0, 0, 0};
    unsigned mw0 = 0, mw1 = 0;

    // bulk helpers; stage rotation: stage(kt, t) = (kt + t) % 3
    auto bulkA_fill = [&](int kt, int s, const __half* hsrc, int t) {
        const __half* asrc = (kt < 8)
            ? (hsrc + ((long)kt * NB + bm) * BK)
            : (g_xB + (((long)t * 2 + (kt - 8)) * NB + bm) * BK);
        bulk_g2s(smb + s * ST_BY, asrc, A_BY, mbb + 8 * s);
    };
    auto bulkB_fill = [&](int kt, int s) {
        bulk_g2s(smb + s * ST_BY + A_BY, g_MB + ((long)kt * NG + bn) * BK, B_BY, mbb + 8 * s);
    };

    // t=0 prologue: full fills for kt0 (stage 0), kt1 (stage 1)
    if (tid == 0) {
        mbar_expect_tx(mbb + 0, (unsigned)ST_BY);
        bulkB_fill(0, 0);
        bulkA_fill(0, 0, g_h, 0);
        mbar_expect_tx(mbb + 8, (unsigned)ST_BY);
        bulkB_fill(1, 1);
        bulkA_fill(1, 1, g_h, 0);
    }

    for (int t = 0; t < NT; ++t) {
        const int cur = t & 1;
        const __half* __restrict__ hsrc = g_h + cur * HSZ;
        __half* __restrict__ hdst = g_h + (cur ^ 1) * HSZ;

        // post-barrier A fills (B + expect_tx issued pre-barrier last step)
        if (t > 0 && tid == 0) {
            bulkA_fill(0, t % 3, hsrc, t);
            bulkA_fill(1, (t + 1) % 3, hsrc, t);
        }
        if ((t & 31) == 0) {
            mw0 = g_maskw[bgA * 16 + (t >> 5)];
            mw1 = g_maskw[bgB * 16 + (t >> 5)];
        }

        float acc[2][4][4];
#pragma unroll
        for (int i = 0; i < 2; ++i)
#pragma unroll
            for (int j = 0; j < 4; ++j)
#pragma unroll
                for (int k = 0; k < 4; ++k) acc[i][j][k] = 0.0f;

        for (int kt = 0; kt < NKT; ++kt) {
            const int s = (kt + t) % NST;
            mbar_wait(mbb + 8 * s, (unsigned)ph[s]);
            ph[s] ^= 1;
            __syncthreads();  // all warps done with kt-1 -> stage of kt+2 reusable
            if (tid == 0 && kt + 2 < NKT) {
                const int s2 = (kt + 2 + t) % NST;
                mbar_expect_tx(mbb + 8 * s2, (unsigned)ST_BY);
                bulkB_fill(kt + 2, s2);
                bulkA_fill(kt + 2, s2, hsrc, t);
            }

            const __half* Ab = sh + s * ST_H;
            const __half* arow = Ab + (wm * 32 + g) * BK;
            const __half* brow = Ab + A_H + (wn * 32 + g) * BK;
#pragma unroll
            for (int ch = 0; ch < 8; ++ch) {
                const int o = ((ch ^ g) << 4) + c4;
                uint2 aA = *(const uint2*)(arow + o);
                uint2 aB = *(const uint2*)(arow + 1024 + o);
                uint2 aC = *(const uint2*)(arow + 2048 + o);
                uint2 aD = *(const uint2*)(arow + 3072 + o);
                uint2 b0 = *(const uint2*)(brow + o);
                uint2 b1 = *(const uint2*)(brow + 1024 + o);
                uint2 b2 = *(const uint2*)(brow + 2048 + o);
                uint2 b3 = *(const uint2*)(brow + 3072 + o);
                mma16(acc[0][0], aA.x, aB.x, aA.y, aB.y, b0.x, b0.y);
                mma16(acc[0][1], aA.x, aB.x, aA.y, aB.y, b1.x, b1.y);
                mma16(acc[0][2], aA.x, aB.x, aA.y, aB.y, b2.x, b2.y);
                mma16(acc[0][3], aA.x, aB.x, aA.y, aB.y, b3.x, b3.y);
                mma16(acc[1][0], aC.x, aD.x, aC.y, aD.y, b0.x, b0.y);
                mma16(acc[1][1], aC.x, aD.x, aC.y, aD.y, b1.x, b1.y);
                mma16(acc[1][2], aC.x, aD.x, aC.y, aD.y, b2.x, b2.y);
                mma16(acc[1][3], aC.x, aD.x, aC.y, aD.y, b3.x, b3.y);
            }
        }

        // register-state epilogue (shuffle gate quads; no smem, no sync)
        const unsigned bit0 = (mw0 >> (t & 31)) & 1u;
        const unsigned bit1 = (mw1 >> (t & 31)) & 1u;
#pragma unroll
        for (int i = 0; i < 8; ++i) {
            const int mt = i >> 2, nt = i & 3;
            float v0 = acc[mt][nt][0], v1 = acc[mt][nt][1];
            float v2 = acc[mt][nt][2], v3 = acc[mt][nt][3];
            float sx = odd ? v0 : v2;
            float sy = odd ? v1 : v3;
            float gx = __shfl_xor_sync(0xffffffffu, sx, 1);
            float gy = __shfl_xor_sync(0xffffffffu, sy, 1);
            float zi, zf, zg, zo;
            if (!odd) { zi = v0; zf = v1; zg = gx; zo = gy; }
            else      { zi = gx; zf = gy; zg = v2; zo = v3; }
            float4 bb = b4[nt];
            zi += bb.x; zf += bb.y; zg += bb.z; zo += bb.w;
            float iv = sigmf(zi), fv = sigmf(zf), gv = tanhfa(zg), ov = sigmf(zo);
            float cn = fv * cst[i] + iv * gv;
            float hn = ov * tanhfa(cn);
            unsigned msk = mt ? bit1 : bit0;
            if (!msk) { cn = cst[i]; hn = hst[i]; }
            cst[i] = cn;
            hst[i] = hn;
            hdst[mt ? hposB[nt] : hposA[nt]] = __float2half_rn(hn);
        }

        // pre-barrier: next step's WEIGHT fills + expect_tx (stages provably idle:
        // stage (t+1)%3 last read kt7, (t+2)%3 last read kt8; both done before sync@kt9)
        if (t + 1 < NT && tid == 0) {
            const int sA = (t + 1) % 3, sB = (t + 2) % 3;
            mbar_expect_tx(mbb + 8 * sA, (unsigned)ST_BY);
            bulkB_fill(0, sA);
            mbar_expect_tx(mbb + 8 * sB, (unsigned)ST_BY);
            bulkB_fill(1, sB);
        }

        grid_barrier();
    }

    // final c (fp32) for the MLP head
#pragma unroll
    for (int i = 0; i < 8; ++i) {
        int bg = (i >> 2) ? bgB : bgA;
        g_cf[(long)bg * NH + jj[i & 3]] = cst[i];
    }
    if (tid == 0)
        for (int s = 0; s < NST; ++s) mbar_inval(mbb + 8 * s);
}

// un-permute/un-swizzle final h (buffer 0 after 512 steps) to fp32
__global__ void __launch_bounds__(256) unperm_h() {
    int idx = blockIdx.x * 256 + threadIdx.x; // NB*NH
    int b = idx >> 10, j = idx & 1023;
    int q = (j & ~15) | c_pinv[j & 15];
    int kb = q >> 7, hc = q & 127;
    long off = (((long)kb * NB + b) << 7) + (((hc >> 4) ^ (b & 7)) << 4) + (hc & 15);
    g_hf[idx] = __half2float(g_h[off]);
}

// ---------------- MLP head ----------------
__global__ void __launch_bounds__(256) mlp1_kernel(const float* __restrict__ b1) {
    __shared__ float a_s[64 * 20];
    __shared__ float b_s[16 * 68];
    int tid = threadIdx.x;
    int bn = blockIdx.x * 64, bm = blockIdx.y * 64;
    int ty = tid >> 4, tx = tid & 15;
    float acc[4][4];
#pragma unroll
    for (int i = 0; i < 4; ++i)
#pragma unroll
        for (int j = 0; j < 4; ++j) acc[i][j] = 0.0f;

    for (int kt = 0; kt < 128; ++kt) {
        int k0 = kt * 16;
        {
            int m = tid >> 2, kq = tid & 3;
            int k = k0 + 4 * kq;
            const float* src = (k < NH) ? (g_hf + (long)(bm + m) * NH + k)
                                        : (g_cf + (long)(bm + m) * NH + (k - NH));
            *(float4*)(a_s + m * 20 + 4 * kq) = *(const float4*)src;
        }
        {
            int kr = tid >> 4, cq = tid & 15;
            *(float4*)(b_s + kr * 68 + 4 * cq) =
                *(const float4*)(g_MLP + (long)(k0 + kr) * NH + bn + 4 * cq);
        }
        __syncthreads();
#pragma unroll
        for (int k = 0; k < 16; ++k) {
            float ar[4], br[4];
#pragma unroll
            for (int i = 0; i < 4; ++i) {
                ar[i] = a_s[(4 * ty + i) * 20 + k];
                br[i] = b_s[k * 68 + 4 * tx + i];
            }
#pragma unroll
            for (int i = 0; i < 4; ++i)
#pragma unroll
                for (int j = 0; j < 4; ++j) acc[i][j] += ar[i] * br[j];
        }
        __syncthreads();
    }
#pragma unroll
    for (int i = 0; i < 4; ++i)
#pragma unroll
        for (int j = 0; j < 4; ++j) {
            float v = acc[i][j] + b1[bn + 4 * tx + j];
            v = v > 0.0f ? v : 0.2f * v;
            g_y1[(long)(bm + 4 * ty + i) * NH + bn + 4 * tx + j] = v;
        }
}

__global__ void __launch_bounds__(64) mlp2_kernel(
    const float* __restrict__ W2, const float* __restrict__ b2, float* __restrict__ out) {
    __shared__ float row[NH];
    int bg = blockIdx.x;
    int o = threadIdx.x;
    for (int i = o; i < NH; i += 64) row[i] = g_y1[(long)bg * NH + i];
    __syncthreads();
    float acc = b2[o];
#pragma unroll 8
    for (int k = 0; k < NH; ++k) acc += row[k] * W2[(long)k * NOUT + o];
    out[(long)bg * NOUT + o] = acc;
}

// ---------------- launch ----------------
extern "C" void kernel_launch(void* const* d_in, const int* in_sizes, int n_in,
                              void* d_out, int out_size) {
    const float* x  = (const float*)d_in[0];
    const float* W  = (const float*)d_in[1];
    const float* U  = (const float*)d_in[2];
    const float* b  = (const float*)d_in[3];
    const float* W1 = (const float*)d_in[4];
    const float* b1 = (const float*)d_in[5];
    const float* W2 = (const float*)d_in[6];
    const float* b2 = (const float*)d_in[7];
    float* out = (float*)d_out;

    cudaFuncSetAttribute(lstm_persistent,
                         cudaFuncAttributeMaxDynamicSharedMemorySize, SMEM_BYTES);

    const long WN = (long)10 * NG * 128;
    const long MN = (long)NT * 2 * NB * 8 + (long)2048 * NH + (long)HSZ / 8;

    // lstm_persistent is the 4th launch (ncu profiles launch index 3)
    mask_kernel<<<(NB * NT * 32) / 256, 256>>>(x);
    prep_weights<<<(int)(WN / 256), 256>>>(W, U, b);
    prep_misc<<<(int)((MN + 255) / 256), 256>>>(x, W1);
    lstm_persistent<<<dim3(NG / BN, NB / BM), 256, SMEM_BYTES>>>();
    unperm_h<<<(NB * NH) / 256, 256>>>();
    mlp1_kernel<<<dim3(NH / 64, NB / 64), 256>>>(b1);
    mlp2_kernel<<<NB, 64>>>(W2, b2, out);
}